// round 6
// baseline (speedup 1.0000x reference)
#include <cuda_runtime.h>
#include <cuda_fp16.h>
#include <mma.h>
#include <math.h>
#include <stdint.h>

using namespace nvcuda;

// Problem dims
#define S_LEN 256
#define B_SZ  128
#define D1    1024
#define N2    2048
#define M_ROWS (S_LEN * B_SZ)   // 32768

// ---------------- device scratch (static; no allocations allowed) ----------------
__device__ __half g_Ah[(size_t)M_ROWS * D1];     // f1_seq in fp16            (64 MB)
__device__ __half g_Wt[(size_t)N2 * D1];         // [W11a|W12a]^T : [n][k]    (4 MB)
__device__ __half g_Wbh[(size_t)N2 * N2];        // blockdiag(W11b, W12b)     (8 MB)
__device__ __half g_A2h[(size_t)B_SZ * N2];      // [f1 | f2] fp16
__device__ float  g_c[(size_t)B_SZ * N2];        // bias + S-independent pre-activation
__device__ float  g_wv[N2];                      // [W21 | W22]
__device__ float  g_logit[2 * M_ROWS];           // s1, s2 logits
__device__ float  g_coef[M_ROWS];                // (w1+w2)*0.5/S

// ---------------- PTX helpers (all sm_80-era; safe under compute_100) ----------------
__device__ __forceinline__ uint32_t smem_u32(const void* p) {
    uint32_t a;
    asm("{ .reg .u64 t; cvta.to.shared.u64 t, %1; cvt.u32.u64 %0, t; }" : "=r"(a) : "l"(p));
    return a;
}
__device__ __forceinline__ void cp16(uint32_t s, const void* g) {
    asm volatile("cp.async.cg.shared.global [%0], [%1], 16;" :: "r"(s), "l"(g));
}
__device__ __forceinline__ void cp_commit() { asm volatile("cp.async.commit_group;" ::: "memory"); }
__device__ __forceinline__ void ldsm4(uint32_t& r0, uint32_t& r1, uint32_t& r2, uint32_t& r3,
                                      uint32_t addr) {
    asm volatile("ldmatrix.sync.aligned.m8n8.x4.shared.b16 {%0,%1,%2,%3}, [%4];"
                 : "=r"(r0), "=r"(r1), "=r"(r2), "=r"(r3) : "r"(addr));
}
__device__ __forceinline__ void mma16816(float* c, uint32_t a0, uint32_t a1, uint32_t a2,
                                         uint32_t a3, uint32_t b0, uint32_t b1) {
    asm volatile(
        "mma.sync.aligned.m16n8k16.row.col.f32.f16.f16.f32 "
        "{%0,%1,%2,%3}, {%4,%5,%6,%7}, {%8,%9}, {%0,%1,%2,%3};"
        : "+f"(c[0]), "+f"(c[1]), "+f"(c[2]), "+f"(c[3])
        : "r"(a0), "r"(a1), "r"(a2), "r"(a3), "r"(b0), "r"(b1));
}
__device__ __forceinline__ float tanh_fast(float x) {
    float t;
    asm("tanh.approx.f32 %0, %1;" : "=f"(t) : "f"(x));
    return t;
}

// ---------------- prep kernels ----------------
// One merged kernel: g_c = bias, g_A2h = [f1|f2], g_logit = 0, g_wv = [W21|W22]
__global__ void prep_kernel(const float* __restrict__ f1, const float* __restrict__ f2,
                            const float* __restrict__ b11, const float* __restrict__ b12,
                            const float* __restrict__ W21, const float* __restrict__ W22) {
    int stride = gridDim.x * blockDim.x;
    int gid = blockIdx.x * blockDim.x + threadIdx.x;
    for (int i = gid; i < B_SZ * N2; i += stride) {
        int b = i >> 11, k = i & (N2 - 1);
        float bias, v;
        if (k < D1) { bias = b11[k]; v = f1[b * D1 + k]; }
        else        { bias = b12[k - D1]; v = f2[b * D1 + (k - D1)]; }
        g_c[i] = bias;
        g_A2h[i] = __float2half_rn(v);
    }
    for (int i = gid; i < 2 * M_ROWS; i += stride) g_logit[i] = 0.f;
    for (int i = gid; i < N2; i += stride)
        g_wv[i] = (i < D1) ? W21[i] : W22[i - D1];
}

__global__ void convA_kernel(const float* __restrict__ fseq) {
    size_t n4 = (size_t)M_ROWS * D1 / 4;
    const float4* src = (const float4*)fseq;
    __half2* dst = (__half2*)g_Ah;
    for (size_t i = blockIdx.x * (size_t)blockDim.x + threadIdx.x; i < n4;
         i += (size_t)gridDim.x * blockDim.x) {
        float4 v = src[i];
        dst[2 * i]     = __floats2half2_rn(v.x, v.y);
        dst[2 * i + 1] = __floats2half2_rn(v.z, v.w);
    }
}

__global__ void convWt_kernel(const float* __restrict__ W11, const float* __restrict__ W12) {
    // g_Wt[n][k] = (n<1024) ? W11[k][n] : W12[k][n-1024]   (rows k=0..1023)
    int n = N2 * D1;
    for (int i = blockIdx.x * blockDim.x + threadIdx.x; i < n; i += gridDim.x * blockDim.x) {
        int r = i >> 10, k = i & (D1 - 1);
        float v = (r < D1) ? W11[(size_t)k * D1 + r] : W12[(size_t)k * D1 + (r - D1)];
        g_Wt[i] = __float2half_rn(v);
    }
}

__global__ void convWb_kernel(const float* __restrict__ W11, const float* __restrict__ W12) {
    size_t n = (size_t)N2 * N2;
    for (size_t i = blockIdx.x * (size_t)blockDim.x + threadIdx.x; i < n;
         i += (size_t)gridDim.x * blockDim.x) {
        int k = (int)(i >> 11), c = (int)(i & (N2 - 1));
        float v = 0.f;
        if (k < D1 && c < D1)        v = W11[(size_t)(D1 + k) * D1 + c];
        else if (k >= D1 && c >= D1) v = W12[(size_t)k * D1 + (c - D1)];
        g_Wbh[i] = __float2half_rn(v);
    }
}

// ---------------- small GEMM (wmma): c[b,n] += [f1|f2] @ blockdiag, split-K ----------------
#define BMs 128
#define BNs 128
#define BKs 32
#define CSM_LD 136
#define SMEM_BYTES_S (BMs * CSM_LD * 4)

__global__ void __launch_bounds__(256) small_gemm_kernel() {
    extern __shared__ char smem_raw[];
    __half* As = (__half*)smem_raw;
    __half* Bs = As + BMs * BKs;
    float*  Csm = (float*)smem_raw;

    const int tid = threadIdx.x;
    const int n0 = blockIdx.x * BNs;
    const int warpId = tid >> 5;
    const int wm0 = (warpId >> 1) * 32;
    const int wn0 = (warpId & 1) * 64;
    const int ktbase = blockIdx.z * 8;

    wmma::fragment<wmma::accumulator, 16, 16, 16, float> acc[2][4];
#pragma unroll
    for (int mi = 0; mi < 2; mi++)
#pragma unroll
        for (int ni = 0; ni < 4; ni++) wmma::fill_fragment(acc[mi][ni], 0.f);

    for (int kt = 0; kt < 8; kt++) {
        int k0 = (ktbase + kt) * BKs;
#pragma unroll
        for (int t = 0; t < 2; t++) {
            int v = tid + t * 256;
            int r = v >> 2, c = (v & 3) * 8;
            *(uint4*)(As + r * BKs + c) = *(const uint4*)(g_A2h + (size_t)r * N2 + k0 + c);
        }
#pragma unroll
        for (int t = 0; t < 2; t++) {
            int v = tid + t * 256;
            int r = v >> 4, c = (v & 15) * 8;
            *(uint4*)(Bs + r * BNs + c) = *(const uint4*)(g_Wbh + (size_t)(k0 + r) * N2 + n0 + c);
        }
        __syncthreads();
#pragma unroll
        for (int kk = 0; kk < 2; kk++) {
            wmma::fragment<wmma::matrix_a, 16, 16, 16, __half, wmma::row_major> af[2];
            wmma::fragment<wmma::matrix_b, 16, 16, 16, __half, wmma::row_major> bf[4];
#pragma unroll
            for (int mi = 0; mi < 2; mi++)
                wmma::load_matrix_sync(af[mi], As + (wm0 + mi * 16) * BKs + kk * 16, BKs);
#pragma unroll
            for (int ni = 0; ni < 4; ni++)
                wmma::load_matrix_sync(bf[ni], Bs + (kk * 16) * BNs + wn0 + ni * 16, BNs);
#pragma unroll
            for (int mi = 0; mi < 2; mi++)
#pragma unroll
                for (int ni = 0; ni < 4; ni++)
                    wmma::mma_sync(acc[mi][ni], af[mi], bf[ni], acc[mi][ni]);
        }
        __syncthreads();
    }
#pragma unroll
    for (int mi = 0; mi < 2; mi++)
#pragma unroll
        for (int ni = 0; ni < 4; ni++)
            wmma::store_matrix_sync(Csm + (wm0 + mi * 16) * CSM_LD + wn0 + ni * 16,
                                    acc[mi][ni], CSM_LD, wmma::mem_row_major);
    __syncthreads();
    for (int idx = tid; idx < BMs * BNs; idx += 256) {
        int r = idx >> 7, c = idx & 127;
        atomicAdd(&g_c[r * N2 + n0 + c], Csm[r * CSM_LD + c]);
    }
}

// ---------------- main GEMM: mma.sync 256x128 tile, 64x64 warp tile --------------
// C = g_Ah[32768,1024] @ g_Wt^T -> logits. BK=64, 3-stage cp.async, prefetch dist 2.
#define KCHUNK 64
#define NCHUNKS 16                         // 1024 / 64
#define NSTAGE 3
#define LDS_PAD 72                         // halfs per row (64 + 8)
#define BM_M 256
#define BN_M 128
#define A_SZ (BM_M * LDS_PAD * 2)          // 36864 B
#define B_SZB (BN_M * LDS_PAD * 2)         // 18432 B
#define STAGE_BYTES (A_SZ + B_SZB)         // 55296 B
#define SMEM_BYTES_MAIN (NSTAGE * STAGE_BYTES)  // 165888 B

__device__ __forceinline__ void load_chunk(uint32_t sbase, int st, int kt, int m0, int n0,
                                           int tid) {
    uint32_t abase = sbase + st * STAGE_BYTES;
    uint32_t bbase = abase + A_SZ;
    const __half* Ag = g_Ah + (size_t)m0 * D1 + kt * KCHUNK;
    const __half* Bg = g_Wt + (size_t)n0 * D1 + kt * KCHUNK;
#pragma unroll
    for (int j = 0; j < 8; j++) {          // A: 256 rows x 8 x 16B
        int idx = tid + j * 256;
        int r = idx >> 3, cc = idx & 7;
        cp16(abase + (r * LDS_PAD + cc * 8) * 2, Ag + (size_t)r * D1 + cc * 8);
    }
#pragma unroll
    for (int j = 0; j < 4; j++) {          // B: 128 rows x 8 x 16B
        int idx = tid + j * 256;
        int r = idx >> 3, cc = idx & 7;
        cp16(bbase + (r * LDS_PAD + cc * 8) * 2, Bg + (size_t)r * D1 + cc * 8);
    }
    cp_commit();
}

__global__ void __launch_bounds__(256, 1) main_gemm_kernel() {
    extern __shared__ char smem[];
    uint32_t sbase = smem_u32(smem);
    const int tid = threadIdx.x;
    const int lane = tid & 31;
    const int wid = tid >> 5;
    const int mw = (wid >> 1) * 64;        // warp M offset (4 warps down, 64 rows each)
    const int nw = (wid & 1) * 64;         // warp N offset (2 warps across, 64 cols each)
    const int m0 = blockIdx.y * BM_M;      // covers s = 2*blockIdx.y .. +1, b = r & 127
    const int n0 = blockIdx.x * BN_M;

    // per-thread ldmatrix offsets (halfs, within stage)
    const uint32_t a_off = (uint32_t)(mw + (lane & 15)) * LDS_PAD + (lane >> 4) * 8;
    const uint32_t b_off = (uint32_t)(nw + (lane & 7) + ((lane >> 4) & 1) * 8) * LDS_PAD +
                           ((lane >> 3) & 1) * 8;

    float acc[4][8][4];
#pragma unroll
    for (int mi = 0; mi < 4; mi++)
#pragma unroll
        for (int ni = 0; ni < 8; ni++)
#pragma unroll
            for (int q = 0; q < 4; q++) acc[mi][ni][q] = 0.f;

    load_chunk(sbase, 0, 0, m0, n0, tid);
    load_chunk(sbase, 1, 1, m0, n0, tid);

    for (int kt = 0; kt < NCHUNKS; kt++) {
        if (kt < NCHUNKS - 1) asm volatile("cp.async.wait_group 1;" ::: "memory");
        else                  asm volatile("cp.async.wait_group 0;" ::: "memory");
        __syncthreads();
        // leading issue: prefetch chunk kt+2 into the stage freed by chunk kt-1
        if (kt + 2 < NCHUNKS) load_chunk(sbase, (kt + 2) % NSTAGE, kt + 2, m0, n0, tid);

        uint32_t sA = sbase + (kt % NSTAGE) * STAGE_BYTES;
        uint32_t sB = sA + A_SZ;
#pragma unroll
        for (int ks = 0; ks < 4; ks++) {
            uint32_t a[4][4];
#pragma unroll
            for (int mi = 0; mi < 4; mi++)
                ldsm4(a[mi][0], a[mi][1], a[mi][2], a[mi][3],
                      sA + (a_off + mi * 16 * LDS_PAD + ks * 16) * 2);
            uint32_t b[4][4];
#pragma unroll
            for (int p = 0; p < 4; p++)
                ldsm4(b[p][0], b[p][1], b[p][2], b[p][3],
                      sB + (b_off + p * 16 * LDS_PAD + ks * 16) * 2);
#pragma unroll
            for (int mi = 0; mi < 4; mi++)
#pragma unroll
                for (int ni = 0; ni < 8; ni++) {
                    int p = ni >> 1, h = (ni & 1) * 2;
                    mma16816(acc[mi][ni], a[mi][0], a[mi][1], a[mi][2], a[mi][3],
                             b[p][h], b[p][h + 1]);
                }
        }
    }

    // ---- register epilogue: tanh(x + c) . wv, reduced over N (bias folded into g_c) ----
    const int gid = lane >> 2, tig = lane & 3;
    int sel = (n0 >= D1) ? M_ROWS : 0;
#pragma unroll
    for (int mi = 0; mi < 4; mi++) {
        float rs0 = 0.f, rs1 = 0.f;
        int r0 = mw + mi * 16 + gid;               // tile row; b = r & 127
        const float* c_row0 = g_c + (size_t)(r0 & 127) * N2;
        const float* c_row1 = g_c + (size_t)((r0 + 8) & 127) * N2;
#pragma unroll
        for (int ni = 0; ni < 8; ni++) {
            int col = n0 + nw + ni * 8 + 2 * tig;
            float2 wv2 = *(const float2*)(g_wv + col);
            float2 c0 = *(const float2*)(c_row0 + col);
            float2 c1 = *(const float2*)(c_row1 + col);
            const float* a = acc[mi][ni];
            rs0 += tanh_fast(a[0] + c0.x) * wv2.x;
            rs0 += tanh_fast(a[1] + c0.y) * wv2.y;
            rs1 += tanh_fast(a[2] + c1.x) * wv2.x;
            rs1 += tanh_fast(a[3] + c1.y) * wv2.y;
        }
        rs0 += __shfl_xor_sync(0xffffffffu, rs0, 1);
        rs0 += __shfl_xor_sync(0xffffffffu, rs0, 2);
        rs1 += __shfl_xor_sync(0xffffffffu, rs1, 1);
        rs1 += __shfl_xor_sync(0xffffffffu, rs1, 2);
        if (tig == 0) {
            atomicAdd(&g_logit[sel + m0 + r0], rs0);
            atomicAdd(&g_logit[sel + m0 + r0 + 8], rs1);
        }
    }
}

// ---------------- softmax over S (per b), combine weights ----------------
__global__ void softmax_kernel() {
    int b = blockIdx.x;
    int s = threadIdx.x;   // 256 threads == S_LEN
    __shared__ float sv1[S_LEN], sv2[S_LEN];
    float v1 = g_logit[s * B_SZ + b];
    float v2 = g_logit[M_ROWS + s * B_SZ + b];
    sv1[s] = v1; sv2[s] = v2;
    __syncthreads();
    float m1 = -1e30f, m2 = -1e30f;
    for (int i = 0; i < S_LEN; i++) { m1 = fmaxf(m1, sv1[i]); m2 = fmaxf(m2, sv2[i]); }
    float z1 = 0.f, z2 = 0.f;
    for (int i = 0; i < S_LEN; i++) { z1 += expf(sv1[i] - m1); z2 += expf(sv2[i] - m2); }
    float w = (expf(v1 - m1) / z1 + expf(v2 - m2) / z2) * 0.5f / (float)S_LEN;
    g_coef[s * B_SZ + b] = w;
}

// ---------------- weighted sum over S (reads fp16 g_Ah, vectorized) ----------------
__global__ void wsum_kernel(float* __restrict__ out) {
    int b = blockIdx.y;
    int d2 = blockIdx.x * 256 + threadIdx.x;   // half2 index: 512 per b
    __shared__ float as[S_LEN];
    for (int i = threadIdx.x; i < S_LEN; i += 256) as[i] = g_coef[i * B_SZ + b];
    __syncthreads();
    const __half2* p = (const __half2*)g_Ah + (size_t)b * (D1 / 2) + d2;
    float ax = 0.f, ay = 0.f;
#pragma unroll 4
    for (int s = 0; s < S_LEN; s++) {
        float2 v = __half22float2(p[(size_t)s * B_SZ * (D1 / 2)]);
        float w = as[s];
        ax += w * v.x; ay += w * v.y;
    }
    float2 r; r.x = ax; r.y = ay;
    *(float2*)(out + (size_t)b * D1 + d2 * 2) = r;
}

// ---------------- launch ----------------
extern "C" void kernel_launch(void* const* d_in, const int* in_sizes, int n_in,
                              void* d_out, int out_size) {
    const float* f1   = (const float*)d_in[0];
    const float* f2   = (const float*)d_in[1];
    const float* fseq = (const float*)d_in[2];
    const float* W11  = (const float*)d_in[3];
    const float* b11  = (const float*)d_in[4];
    const float* W12  = (const float*)d_in[5];
    const float* b12  = (const float*)d_in[6];
    const float* W21  = (const float*)d_in[7];
    const float* W22  = (const float*)d_in[9];
    float* out = (float*)d_out;

    cudaFuncSetAttribute(small_gemm_kernel, cudaFuncAttributeMaxDynamicSharedMemorySize, SMEM_BYTES_S);
    cudaFuncSetAttribute(main_gemm_kernel,  cudaFuncAttributeMaxDynamicSharedMemorySize, SMEM_BYTES_MAIN);

    prep_kernel<<<512, 256>>>(f1, f2, b11, b12, W21, W22);
    convA_kernel<<<4096, 256>>>(fseq);
    convWt_kernel<<<2048, 256>>>(W11, W12);
    convWb_kernel<<<4096, 256>>>(W11, W12);

    // S-independent terms: c[b, 0:2048] += [f1@W11b | f2@W12b]  (split-K over z)
    small_gemm_kernel<<<dim3(16, 1, 8), 256, SMEM_BYTES_S>>>();

    // main fused GEMM (mma.sync, 256x128 tile) + tanh-dot register epilogue -> logits
    main_gemm_kernel<<<dim3(16, 128), 256, SMEM_BYTES_MAIN>>>();

    softmax_kernel<<<128, 256>>>();
    wsum_kernel<<<dim3(2, 128), 256>>>(out);
}

// round 7
// speedup vs baseline: 1.0804x; 1.0804x over previous
#include <cuda_runtime.h>
#include <cuda_fp16.h>
#include <math.h>
#include <stdint.h>

// Problem dims
#define S_LEN 256
#define B_SZ  128
#define D1    1024
#define N2    2048
#define M_ROWS (S_LEN * B_SZ)   // 32768

// ---------------- device scratch (static; no allocations allowed) ----------------
__device__ __half g_Ah[(size_t)M_ROWS * D1];     // f1_seq in fp16            (64 MB)
__device__ __half g_Wt[(size_t)N2 * D1];         // [W11a|W12a]^T : [n][k]    (4 MB)
__device__ __half g_Wbt[(size_t)N2 * D1];        // blockdiag bottom halves^T (4 MB)
__device__ __half g_A2h[(size_t)B_SZ * N2];      // [f1 | f2] fp16
__device__ float  g_c[(size_t)B_SZ * N2];        // bias + S-independent pre-activation
__device__ float  g_wv[N2];                      // [W21 | W22]
__device__ float  g_logit[2 * M_ROWS];           // s1, s2 logits
__device__ float  g_coef[M_ROWS];                // (w1+w2)*0.5/S

// ---------------- PTX helpers (all sm_80-era; safe under compute_100) ----------------
__device__ __forceinline__ uint32_t smem_u32(const void* p) {
    uint32_t a;
    asm("{ .reg .u64 t; cvta.to.shared.u64 t, %1; cvt.u32.u64 %0, t; }" : "=r"(a) : "l"(p));
    return a;
}
__device__ __forceinline__ void cp16(uint32_t s, const void* g) {
    asm volatile("cp.async.cg.shared.global [%0], [%1], 16;" :: "r"(s), "l"(g));
}
__device__ __forceinline__ void cp_commit() { asm volatile("cp.async.commit_group;" ::: "memory"); }
__device__ __forceinline__ void ldsm4(uint32_t& r0, uint32_t& r1, uint32_t& r2, uint32_t& r3,
                                      uint32_t addr) {
    asm volatile("ldmatrix.sync.aligned.m8n8.x4.shared.b16 {%0,%1,%2,%3}, [%4];"
                 : "=r"(r0), "=r"(r1), "=r"(r2), "=r"(r3) : "r"(addr));
}
__device__ __forceinline__ void mma16816(float* c, uint32_t a0, uint32_t a1, uint32_t a2,
                                         uint32_t a3, uint32_t b0, uint32_t b1) {
    asm volatile(
        "mma.sync.aligned.m16n8k16.row.col.f32.f16.f16.f32 "
        "{%0,%1,%2,%3}, {%4,%5,%6,%7}, {%8,%9}, {%0,%1,%2,%3};"
        : "+f"(c[0]), "+f"(c[1]), "+f"(c[2]), "+f"(c[3])
        : "r"(a0), "r"(a1), "r"(a2), "r"(a3), "r"(b0), "r"(b1));
}
__device__ __forceinline__ float tanh_fast(float x) {
    float t;
    asm("tanh.approx.f32 %0, %1;" : "=f"(t) : "f"(x));
    return t;
}

// ---------------- prep: g_A2h = [f1|f2], g_logit = 0, g_wv = [W21|W22] ----------------
__global__ void prep_kernel(const float* __restrict__ f1, const float* __restrict__ f2,
                            const float* __restrict__ W21, const float* __restrict__ W22) {
    int stride = gridDim.x * blockDim.x;
    int gid = blockIdx.x * blockDim.x + threadIdx.x;
    for (int i = gid; i < B_SZ * N2; i += stride) {
        int b = i >> 11, k = i & (N2 - 1);
        float v = (k < D1) ? f1[b * D1 + k] : f2[b * D1 + (k - D1)];
        g_A2h[i] = __float2half_rn(v);
    }
    for (int i = gid; i < 2 * M_ROWS; i += stride) g_logit[i] = 0.f;
    for (int i = gid; i < N2; i += stride)
        g_wv[i] = (i < D1) ? W21[i] : W22[i - D1];
}

__global__ void convA_kernel(const float* __restrict__ fseq) {
    size_t n4 = (size_t)M_ROWS * D1 / 4;
    const float4* src = (const float4*)fseq;
    __half2* dst = (__half2*)g_Ah;
    for (size_t i = blockIdx.x * (size_t)blockDim.x + threadIdx.x; i < n4;
         i += (size_t)gridDim.x * blockDim.x) {
        float4 v = src[i];
        dst[2 * i]     = __floats2half2_rn(v.x, v.y);
        dst[2 * i + 1] = __floats2half2_rn(v.z, v.w);
    }
}

// Merged transpose: g_Wt[n][k] (top halves), g_Wbt[n][k] (bottom halves)
__global__ void convW_kernel(const float* __restrict__ W11, const float* __restrict__ W12) {
    int n = N2 * D1;
    for (int i = blockIdx.x * blockDim.x + threadIdx.x; i < n; i += gridDim.x * blockDim.x) {
        int r = i >> 10, k = i & (D1 - 1);
        float wt, wbt;
        if (r < D1) {
            wt  = W11[(size_t)k * D1 + r];
            wbt = W11[(size_t)(D1 + k) * D1 + r];
        } else {
            wt  = W12[(size_t)k * D1 + (r - D1)];
            wbt = W12[(size_t)(D1 + k) * D1 + (r - D1)];
        }
        g_Wt[i]  = __float2half_rn(wt);
        g_Wbt[i] = __float2half_rn(wbt);
    }
}

// ---------------- shared GEMM tiling (128x128 tile, 32x64 warp tile) --------------
#define KCHUNK 64
#define NCHUNKS 16                         // 1024 / 64
#define NSTAGE 3
#define LDS_PAD 72                         // halfs per row (64 + 8)
#define A_SZ (128 * LDS_PAD * 2)           // 18432 B
#define STAGE_BYTES (2 * A_SZ)             // A + B = 36864 B
#define SMEM_BYTES_MAIN (NSTAGE * STAGE_BYTES)  // 110592 B

// Generic chunk loader: A rows from Ag (lda), B rows from Bg (ldb = D1)
__device__ __forceinline__ void load_chunk_g(uint32_t sbase, int st, const __half* Ag, int lda,
                                             const __half* Bg, int tid) {
    uint32_t abase = sbase + st * STAGE_BYTES;
    uint32_t bbase = abase + A_SZ;
#pragma unroll
    for (int j = 0; j < 4; j++) {          // A: 128 rows x 8 x 16B
        int idx = tid + j * 256;
        int r = idx >> 3, cc = idx & 7;
        cp16(abase + (r * LDS_PAD + cc * 8) * 2, Ag + (size_t)r * lda + cc * 8);
    }
#pragma unroll
    for (int j = 0; j < 4; j++) {          // B: 128 rows x 8 x 16B
        int idx = tid + j * 256;
        int r = idx >> 3, cc = idx & 7;
        cp16(bbase + (r * LDS_PAD + cc * 8) * 2, Bg + (size_t)r * D1 + cc * 8);
    }
    cp_commit();
}

// Shared mainloop: fills acc[2][8][4] for warp tile (mw: 32 rows, nw: 64 cols)
#define GEMM_MAINLOOP(AG, LDA, BG)                                                       \
    load_chunk_g(sbase, 0, (AG), (LDA), (BG), tid);                                      \
    load_chunk_g(sbase, 1, (AG) + KCHUNK, (LDA), (BG) + KCHUNK, tid);                    \
    for (int kt = 0; kt < NCHUNKS; kt++) {                                               \
        if (kt < NCHUNKS - 1) asm volatile("cp.async.wait_group 1;" ::: "memory");       \
        else                  asm volatile("cp.async.wait_group 0;" ::: "memory");       \
        __syncthreads();                                                                 \
        if (kt + 2 < NCHUNKS)                                                            \
            load_chunk_g(sbase, (kt + 2) % NSTAGE, (AG) + (kt + 2) * KCHUNK, (LDA),      \
                         (BG) + (kt + 2) * KCHUNK, tid);                                 \
        uint32_t sA = sbase + (kt % NSTAGE) * STAGE_BYTES;                               \
        uint32_t sB = sA + A_SZ;                                                         \
        _Pragma("unroll")                                                                \
        for (int ks = 0; ks < 4; ks++) {                                                 \
            uint32_t a[2][4];                                                            \
            _Pragma("unroll")                                                            \
            for (int mi = 0; mi < 2; mi++)                                               \
                ldsm4(a[mi][0], a[mi][1], a[mi][2], a[mi][3],                            \
                      sA + (a_off + mi * 16 * LDS_PAD + ks * 16) * 2);                   \
            uint32_t b[4][4];                                                            \
            _Pragma("unroll")                                                            \
            for (int p = 0; p < 4; p++)                                                  \
                ldsm4(b[p][0], b[p][1], b[p][2], b[p][3],                                \
                      sB + (b_off + p * 16 * LDS_PAD + ks * 16) * 2);                    \
            _Pragma("unroll")                                                            \
            for (int mi = 0; mi < 2; mi++)                                               \
                _Pragma("unroll")                                                        \
                for (int ni = 0; ni < 8; ni++) {                                         \
                    int p = ni >> 1, h = (ni & 1) * 2;                                   \
                    mma16816(acc[mi][ni], a[mi][0], a[mi][1], a[mi][2], a[mi][3],        \
                             b[p][h], b[p][h + 1]);                                      \
                }                                                                        \
        }                                                                                \
    }

// ---------------- small GEMM: g_c[b,n] = bias[n] + [f1|f2] @ blockdiag ------------
// grid (16,1): n-tile picks A half (f1 for n<1024, f2 otherwise). Direct store.
__global__ void __launch_bounds__(256, 2) small_gemm_kernel(const float* __restrict__ b11,
                                                            const float* __restrict__ b12) {
    extern __shared__ char smem[];
    uint32_t sbase = smem_u32(smem);
    const int tid = threadIdx.x;
    const int lane = tid & 31;
    const int wid = tid >> 5;
    const int mw = (wid & 3) * 32;
    const int nw = (wid >> 2) * 64;
    const int n0 = blockIdx.x * 128;
    const int aoff = (n0 >= D1) ? D1 : 0;

    const uint32_t a_off = (uint32_t)(mw + (lane & 15)) * LDS_PAD + (lane >> 4) * 8;
    const uint32_t b_off = (uint32_t)(nw + (lane & 7) + ((lane >> 4) & 1) * 8) * LDS_PAD +
                           ((lane >> 3) & 1) * 8;

    float acc[2][8][4];
#pragma unroll
    for (int mi = 0; mi < 2; mi++)
#pragma unroll
        for (int ni = 0; ni < 8; ni++)
#pragma unroll
            for (int q = 0; q < 4; q++) acc[mi][ni][q] = 0.f;

    const __half* Ag = g_A2h + aoff;                    // rows b, lda = N2
    const __half* Bg = g_Wbt + (size_t)n0 * D1;         // rows n, ldb = D1

    GEMM_MAINLOOP(Ag, N2, Bg)

    // direct store epilogue: g_c[r][n0+col] = acc + bias
    const int gid = lane >> 2, tig = lane & 3;
    const float* bb = (n0 >= D1) ? (b12 + (n0 - D1)) : (b11 + n0);
#pragma unroll
    for (int mi = 0; mi < 2; mi++)
#pragma unroll
        for (int ni = 0; ni < 8; ni++) {
            int colL = nw + ni * 8 + 2 * tig;
            int r0 = mw + mi * 16 + gid;
            float2 bv = *(const float2*)(bb + colL);
            const float* a = acc[mi][ni];
            float2 v0; v0.x = a[0] + bv.x; v0.y = a[1] + bv.y;
            float2 v1; v1.x = a[2] + bv.x; v1.y = a[3] + bv.y;
            *(float2*)(g_c + (size_t)r0 * N2 + n0 + colL) = v0;
            *(float2*)(g_c + (size_t)(r0 + 8) * N2 + n0 + colL) = v1;
        }
}

// ---------------- main GEMM: R5 config + fused tanh-dot register epilogue ----------
__global__ void __launch_bounds__(256, 2) main_gemm_kernel() {
    extern __shared__ char smem[];
    uint32_t sbase = smem_u32(smem);
    const int tid = threadIdx.x;
    const int lane = tid & 31;
    const int wid = tid >> 5;
    const int mw = (wid & 3) * 32;         // warp M offset (4 warps down)
    const int nw = (wid >> 2) * 64;        // warp N offset (2 warps across)
    const int m0 = blockIdx.y * 128;       // s tile: rows are b = 0..127
    const int n0 = blockIdx.x * 128;

    const uint32_t a_off = (uint32_t)(mw + (lane & 15)) * LDS_PAD + (lane >> 4) * 8;
    const uint32_t b_off = (uint32_t)(nw + (lane & 7) + ((lane >> 4) & 1) * 8) * LDS_PAD +
                           ((lane >> 3) & 1) * 8;

    float acc[2][8][4];
#pragma unroll
    for (int mi = 0; mi < 2; mi++)
#pragma unroll
        for (int ni = 0; ni < 8; ni++)
#pragma unroll
            for (int q = 0; q < 4; q++) acc[mi][ni][q] = 0.f;

    const __half* Ag = g_Ah + (size_t)m0 * D1;
    const __half* Bg = g_Wt + (size_t)n0 * D1;

    GEMM_MAINLOOP(Ag, D1, Bg)

    // ---- register epilogue: tanh(x + c) . wv, reduced over N (bias folded into g_c) ----
    const int gid = lane >> 2, tig = lane & 3;
    float rs[2][2] = {{0.f, 0.f}, {0.f, 0.f}};
#pragma unroll
    for (int ni = 0; ni < 8; ni++) {
        int col = n0 + nw + ni * 8 + 2 * tig;
        float2 wv2 = *(const float2*)(g_wv + col);
#pragma unroll
        for (int mi = 0; mi < 2; mi++) {
            int r0 = mw + mi * 16 + gid;           // b index (rows of tile)
            float2 c0 = *(const float2*)(g_c + (size_t)r0 * N2 + col);
            float2 c1 = *(const float2*)(g_c + (size_t)(r0 + 8) * N2 + col);
            const float* a = acc[mi][ni];
            rs[mi][0] += tanh_fast(a[0] + c0.x) * wv2.x;
            rs[mi][0] += tanh_fast(a[1] + c0.y) * wv2.y;
            rs[mi][1] += tanh_fast(a[2] + c1.x) * wv2.x;
            rs[mi][1] += tanh_fast(a[3] + c1.y) * wv2.y;
        }
    }
    int sel = (n0 >= D1) ? M_ROWS : 0;
#pragma unroll
    for (int mi = 0; mi < 2; mi++)
#pragma unroll
        for (int h = 0; h < 2; h++) {
            float v = rs[mi][h];
            v += __shfl_xor_sync(0xffffffffu, v, 1);
            v += __shfl_xor_sync(0xffffffffu, v, 2);
            if (tig == 0) {
                int b = mw + mi * 16 + gid + h * 8;
                atomicAdd(&g_logit[sel + blockIdx.y * B_SZ + b], v);
            }
        }
}

// ---------------- softmax over S (per b), combine weights ----------------
__global__ void softmax_kernel() {
    int b = blockIdx.x;
    int s = threadIdx.x;   // 256 threads == S_LEN
    __shared__ float sv1[S_LEN], sv2[S_LEN];
    float v1 = g_logit[s * B_SZ + b];
    float v2 = g_logit[M_ROWS + s * B_SZ + b];
    sv1[s] = v1; sv2[s] = v2;
    __syncthreads();
    float m1 = -1e30f, m2 = -1e30f;
    for (int i = 0; i < S_LEN; i++) { m1 = fmaxf(m1, sv1[i]); m2 = fmaxf(m2, sv2[i]); }
    float z1 = 0.f, z2 = 0.f;
    for (int i = 0; i < S_LEN; i++) { z1 += expf(sv1[i] - m1); z2 += expf(sv2[i] - m2); }
    float w = (expf(v1 - m1) / z1 + expf(v2 - m2) / z2) * 0.5f / (float)S_LEN;
    g_coef[s * B_SZ + b] = w;
}

// ---------------- weighted sum over S (reads fp16 g_Ah, vectorized) ----------------
__global__ void wsum_kernel(float* __restrict__ out) {
    int b = blockIdx.y;
    int d2 = blockIdx.x * 256 + threadIdx.x;   // half2 index: 512 per b
    __shared__ float as[S_LEN];
    for (int i = threadIdx.x; i < S_LEN; i += 256) as[i] = g_coef[i * B_SZ + b];
    __syncthreads();
    const __half2* p = (const __half2*)g_Ah + (size_t)b * (D1 / 2) + d2;
    float ax = 0.f, ay = 0.f;
#pragma unroll 4
    for (int s = 0; s < S_LEN; s++) {
        float2 v = __half22float2(p[(size_t)s * B_SZ * (D1 / 2)]);
        float w = as[s];
        ax += w * v.x; ay += w * v.y;
    }
    float2 r; r.x = ax; r.y = ay;
    *(float2*)(out + (size_t)b * D1 + d2 * 2) = r;
}

// ---------------- launch ----------------
extern "C" void kernel_launch(void* const* d_in, const int* in_sizes, int n_in,
                              void* d_out, int out_size) {
    const float* f1   = (const float*)d_in[0];
    const float* f2   = (const float*)d_in[1];
    const float* fseq = (const float*)d_in[2];
    const float* W11  = (const float*)d_in[3];
    const float* b11  = (const float*)d_in[4];
    const float* W12  = (const float*)d_in[5];
    const float* b12  = (const float*)d_in[6];
    const float* W21  = (const float*)d_in[7];
    const float* W22  = (const float*)d_in[9];
    float* out = (float*)d_out;

    cudaFuncSetAttribute(small_gemm_kernel, cudaFuncAttributeMaxDynamicSharedMemorySize, SMEM_BYTES_MAIN);
    cudaFuncSetAttribute(main_gemm_kernel,  cudaFuncAttributeMaxDynamicSharedMemorySize, SMEM_BYTES_MAIN);

    prep_kernel<<<512, 256>>>(f1, f2, W21, W22);
    convW_kernel<<<2048, 256>>>(W11, W12);
    convA_kernel<<<4096, 256>>>(fseq);

    // S-independent terms: g_c = bias + [f1@W11b | f2@W12b]  (direct store, no atomics)
    small_gemm_kernel<<<dim3(16, 1), 256, SMEM_BYTES_MAIN>>>(b11, b12);

    // main fused GEMM (mma.sync, 128x128 tile) + tanh-dot register epilogue -> logits
    main_gemm_kernel<<<dim3(16, 256), 256, SMEM_BYTES_MAIN>>>();

    softmax_kernel<<<128, 256>>>();
    wsum_kernel<<<dim3(2, 128), 256>>>(out);
}

// round 8
// speedup vs baseline: 1.1386x; 1.0539x over previous
#include <cuda_runtime.h>
#include <cuda_fp16.h>
#include <math.h>
#include <stdint.h>

// Problem dims
#define S_LEN 256
#define B_SZ  128
#define D1    1024
#define N2    2048
#define M_ROWS (S_LEN * B_SZ)   // 32768

// ---------------- device scratch (static; no allocations allowed) ----------------
__device__ __half g_Ah[(size_t)M_ROWS * D1];     // f1_seq in fp16            (64 MB)
__device__ __half g_Wt[(size_t)N2 * D1];         // [W11a|W12a]^T : [n][k]    (4 MB)
__device__ __half g_Wbt[(size_t)N2 * D1];        // blockdiag bottom halves^T (4 MB)
__device__ __half g_A2h[(size_t)B_SZ * N2];      // [f1 | f2] fp16
__device__ float  g_c[(size_t)B_SZ * N2];        // bias + S-independent pre-activation
__device__ float  g_wv[N2];                      // [W21 | W22]
__device__ float  g_logit[2 * M_ROWS];           // s1, s2 logits
__device__ float  g_coef[M_ROWS];                // (w1+w2)*0.5/S

// ---------------- PTX helpers (all sm_80-era; safe under compute_100) ----------------
__device__ __forceinline__ uint32_t smem_u32(const void* p) {
    uint32_t a;
    asm("{ .reg .u64 t; cvta.to.shared.u64 t, %1; cvt.u32.u64 %0, t; }" : "=r"(a) : "l"(p));
    return a;
}
__device__ __forceinline__ void cp16(uint32_t s, const void* g) {
    asm volatile("cp.async.cg.shared.global [%0], [%1], 16;" :: "r"(s), "l"(g));
}
__device__ __forceinline__ void cp_commit() { asm volatile("cp.async.commit_group;" ::: "memory"); }
__device__ __forceinline__ void ldsm4(uint32_t& r0, uint32_t& r1, uint32_t& r2, uint32_t& r3,
                                      uint32_t addr) {
    asm volatile("ldmatrix.sync.aligned.m8n8.x4.shared.b16 {%0,%1,%2,%3}, [%4];"
                 : "=r"(r0), "=r"(r1), "=r"(r2), "=r"(r3) : "r"(addr));
}
__device__ __forceinline__ void mma16816(float* c, uint32_t a0, uint32_t a1, uint32_t a2,
                                         uint32_t a3, uint32_t b0, uint32_t b1) {
    asm volatile(
        "mma.sync.aligned.m16n8k16.row.col.f32.f16.f16.f32 "
        "{%0,%1,%2,%3}, {%4,%5,%6,%7}, {%8,%9}, {%0,%1,%2,%3};"
        : "+f"(c[0]), "+f"(c[1]), "+f"(c[2]), "+f"(c[3])
        : "r"(a0), "r"(a1), "r"(a2), "r"(a3), "r"(b0), "r"(b1));
}
__device__ __forceinline__ float tanh_fast(float x) {
    float t;
    asm("tanh.approx.f32 %0, %1;" : "=f"(t) : "f"(x));
    return t;
}

// ---------------- prep: g_A2h = [f1|f2], g_c = bias, g_logit = 0, g_wv ----------------
__global__ void prep_kernel(const float* __restrict__ f1, const float* __restrict__ f2,
                            const float* __restrict__ b11, const float* __restrict__ b12,
                            const float* __restrict__ W21, const float* __restrict__ W22) {
    int stride = gridDim.x * blockDim.x;
    int gid = blockIdx.x * blockDim.x + threadIdx.x;
    for (int i = gid; i < B_SZ * N2; i += stride) {
        int b = i >> 11, k = i & (N2 - 1);
        float v, bias;
        if (k < D1) { v = f1[b * D1 + k]; bias = b11[k]; }
        else        { v = f2[b * D1 + (k - D1)]; bias = b12[k - D1]; }
        g_A2h[i] = __float2half_rn(v);
        g_c[i] = bias;
    }
    for (int i = gid; i < 2 * M_ROWS; i += stride) g_logit[i] = 0.f;
    for (int i = gid; i < N2; i += stride)
        g_wv[i] = (i < D1) ? W21[i] : W22[i - D1];
}

__global__ void convA_kernel(const float* __restrict__ fseq) {
    size_t n4 = (size_t)M_ROWS * D1 / 4;
    const float4* src = (const float4*)fseq;
    __half2* dst = (__half2*)g_Ah;
    for (size_t i = blockIdx.x * (size_t)blockDim.x + threadIdx.x; i < n4;
         i += (size_t)gridDim.x * blockDim.x) {
        float4 v = src[i];
        dst[2 * i]     = __floats2half2_rn(v.x, v.y);
        dst[2 * i + 1] = __floats2half2_rn(v.z, v.w);
    }
}

// Tiled transpose: g_Wt[n][k] = W[k][n] (top halves), g_Wbt[n][k] = W[1024+k][n].
// Block (32,8): 32x32 tile, both reads and writes coalesced, smem pad 33.
__global__ void convW_kernel(const float* __restrict__ W11, const float* __restrict__ W12) {
    __shared__ float st[32][33], sb[32][33];
    int k0 = blockIdx.x * 32;             // k tile (0..1023)
    int n0 = blockIdx.y * 32;             // n tile (0..2047)
    const float* W = (n0 < D1) ? W11 : W12;
    int nc = (n0 < D1) ? n0 : n0 - D1;    // column within source
    int tx = threadIdx.x, ty = threadIdx.y;
#pragma unroll
    for (int j = 0; j < 4; j++) {
        int k = k0 + ty + j * 8;
        st[ty + j * 8][tx] = W[(size_t)k * D1 + nc + tx];
        sb[ty + j * 8][tx] = W[(size_t)(D1 + k) * D1 + nc + tx];
    }
    __syncthreads();
#pragma unroll
    for (int j = 0; j < 4; j++) {
        int n = n0 + ty + j * 8;
        g_Wt[(size_t)n * D1 + k0 + tx]  = __float2half_rn(st[tx][ty + j * 8]);
        g_Wbt[(size_t)n * D1 + k0 + tx] = __float2half_rn(sb[tx][ty + j * 8]);
    }
}

// ---------------- shared GEMM tiling (128x128 tile, 32x64 warp tile) --------------
#define KCHUNK 64
#define NCHUNKS 16                         // 1024 / 64
#define NSTAGE 3
#define LDS_PAD 72                         // halfs per row (64 + 8)
#define A_SZ (128 * LDS_PAD * 2)           // 18432 B
#define STAGE_BYTES (2 * A_SZ)             // A + B = 36864 B
#define SMEM_BYTES_MAIN (NSTAGE * STAGE_BYTES)  // 110592 B

__device__ __forceinline__ void load_chunk_g(uint32_t sbase, int st, const __half* Ag, int lda,
                                             const __half* Bg, int tid) {
    uint32_t abase = sbase + st * STAGE_BYTES;
    uint32_t bbase = abase + A_SZ;
#pragma unroll
    for (int j = 0; j < 4; j++) {          // A: 128 rows x 8 x 16B
        int idx = tid + j * 256;
        int r = idx >> 3, cc = idx & 7;
        cp16(abase + (r * LDS_PAD + cc * 8) * 2, Ag + (size_t)r * lda + cc * 8);
    }
#pragma unroll
    for (int j = 0; j < 4; j++) {          // B: 128 rows x 8 x 16B
        int idx = tid + j * 256;
        int r = idx >> 3, cc = idx & 7;
        cp16(bbase + (r * LDS_PAD + cc * 8) * 2, Bg + (size_t)r * D1 + cc * 8);
    }
    cp_commit();
}

// Shared 3-stage pipelined mainloop over NC chunks of K=64.
template <int NC>
__device__ __forceinline__ void gemm_mainloop(float acc[2][8][4], uint32_t sbase,
                                              uint32_t a_off, uint32_t b_off,
                                              const __half* Ag, int lda, const __half* Bg,
                                              int tid) {
    load_chunk_g(sbase, 0, Ag, lda, Bg, tid);
    if (NC > 1) load_chunk_g(sbase, 1, Ag + KCHUNK, lda, Bg + KCHUNK, tid);
    for (int kt = 0; kt < NC; kt++) {
        if (kt < NC - 1) asm volatile("cp.async.wait_group 1;" ::: "memory");
        else             asm volatile("cp.async.wait_group 0;" ::: "memory");
        __syncthreads();
        if (kt + 2 < NC)
            load_chunk_g(sbase, (kt + 2) % NSTAGE, Ag + (kt + 2) * KCHUNK, lda,
                         Bg + (kt + 2) * KCHUNK, tid);
        uint32_t sA = sbase + (kt % NSTAGE) * STAGE_BYTES;
        uint32_t sB = sA + A_SZ;
#pragma unroll
        for (int ks = 0; ks < 4; ks++) {
            uint32_t a[2][4];
#pragma unroll
            for (int mi = 0; mi < 2; mi++)
                ldsm4(a[mi][0], a[mi][1], a[mi][2], a[mi][3],
                      sA + (a_off + mi * 16 * LDS_PAD + ks * 16) * 2);
            uint32_t b[4][4];
#pragma unroll
            for (int p = 0; p < 4; p++)
                ldsm4(b[p][0], b[p][1], b[p][2], b[p][3],
                      sB + (b_off + p * 16 * LDS_PAD + ks * 16) * 2);
#pragma unroll
            for (int mi = 0; mi < 2; mi++)
#pragma unroll
                for (int ni = 0; ni < 8; ni++) {
                    int p = ni >> 1, h = (ni & 1) * 2;
                    mma16816(acc[mi][ni], a[mi][0], a[mi][1], a[mi][2], a[mi][3],
                             b[p][h], b[p][h + 1]);
                }
        }
    }
}

// ---------------- small GEMM: g_c += [f1|f2] @ blockdiag, split-K 8 -------------
// grid (16, 1, 8): z = K-split (2 chunks each). Atomic accumulate onto bias-init g_c.
__global__ void __launch_bounds__(256, 2) small_gemm_kernel() {
    extern __shared__ char smem[];
    uint32_t sbase = smem_u32(smem);
    const int tid = threadIdx.x;
    const int lane = tid & 31;
    const int wid = tid >> 5;
    const int mw = (wid & 3) * 32;
    const int nw = (wid >> 2) * 64;
    const int n0 = blockIdx.x * 128;
    const int kz = blockIdx.z * 2;                      // chunk base
    const int aoff = (n0 >= D1) ? D1 : 0;

    const uint32_t a_off = (uint32_t)(mw + (lane & 15)) * LDS_PAD + (lane >> 4) * 8;
    const uint32_t b_off = (uint32_t)(nw + (lane & 7) + ((lane >> 4) & 1) * 8) * LDS_PAD +
                           ((lane >> 3) & 1) * 8;

    float acc[2][8][4];
#pragma unroll
    for (int mi = 0; mi < 2; mi++)
#pragma unroll
        for (int ni = 0; ni < 8; ni++)
#pragma unroll
            for (int q = 0; q < 4; q++) acc[mi][ni][q] = 0.f;

    const __half* Ag = g_A2h + aoff + kz * KCHUNK;            // rows b, lda = N2
    const __half* Bg = g_Wbt + (size_t)n0 * D1 + kz * KCHUNK; // rows n, ldb = D1

    gemm_mainloop<2>(acc, sbase, a_off, b_off, Ag, N2, Bg, tid);

    const int gid = lane >> 2, tig = lane & 3;
#pragma unroll
    for (int mi = 0; mi < 2; mi++)
#pragma unroll
        for (int ni = 0; ni < 8; ni++) {
            int colL = nw + ni * 8 + 2 * tig;
            int r0 = mw + mi * 16 + gid;
            const float* a = acc[mi][ni];
            float* p0 = g_c + (size_t)r0 * N2 + n0 + colL;
            float* p1 = g_c + (size_t)(r0 + 8) * N2 + n0 + colL;
            atomicAdd(p0, a[0]);     atomicAdd(p0 + 1, a[1]);
            atomicAdd(p1, a[2]);     atomicAdd(p1 + 1, a[3]);
        }
}

// ---------------- main GEMM + fused tanh-dot register epilogue ----------
__global__ void __launch_bounds__(256, 2) main_gemm_kernel() {
    extern __shared__ char smem[];
    uint32_t sbase = smem_u32(smem);
    const int tid = threadIdx.x;
    const int lane = tid & 31;
    const int wid = tid >> 5;
    const int mw = (wid & 3) * 32;         // warp M offset (4 warps down)
    const int nw = (wid >> 2) * 64;        // warp N offset (2 warps across)
    const int m0 = blockIdx.y * 128;       // s tile: rows are b = 0..127
    const int n0 = blockIdx.x * 128;

    const uint32_t a_off = (uint32_t)(mw + (lane & 15)) * LDS_PAD + (lane >> 4) * 8;
    const uint32_t b_off = (uint32_t)(nw + (lane & 7) + ((lane >> 4) & 1) * 8) * LDS_PAD +
                           ((lane >> 3) & 1) * 8;

    float acc[2][8][4];
#pragma unroll
    for (int mi = 0; mi < 2; mi++)
#pragma unroll
        for (int ni = 0; ni < 8; ni++)
#pragma unroll
            for (int q = 0; q < 4; q++) acc[mi][ni][q] = 0.f;

    const __half* Ag = g_Ah + (size_t)m0 * D1;
    const __half* Bg = g_Wt + (size_t)n0 * D1;

    gemm_mainloop<NCHUNKS>(acc, sbase, a_off, b_off, Ag, D1, Bg, tid);

    // ---- register epilogue: tanh(x + c) . wv, reduced over N (bias folded into g_c) ----
    const int gid = lane >> 2, tig = lane & 3;
    float rs[2][2] = {{0.f, 0.f}, {0.f, 0.f}};
#pragma unroll
    for (int ni = 0; ni < 8; ni++) {
        int col = n0 + nw + ni * 8 + 2 * tig;
        float2 wv2 = *(const float2*)(g_wv + col);
#pragma unroll
        for (int mi = 0; mi < 2; mi++) {
            int r0 = mw + mi * 16 + gid;           // b index (rows of tile)
            float2 c0 = *(const float2*)(g_c + (size_t)r0 * N2 + col);
            float2 c1 = *(const float2*)(g_c + (size_t)(r0 + 8) * N2 + col);
            const float* a = acc[mi][ni];
            rs[mi][0] += tanh_fast(a[0] + c0.x) * wv2.x;
            rs[mi][0] += tanh_fast(a[1] + c0.y) * wv2.y;
            rs[mi][1] += tanh_fast(a[2] + c1.x) * wv2.x;
            rs[mi][1] += tanh_fast(a[3] + c1.y) * wv2.y;
        }
    }
    int sel = (n0 >= D1) ? M_ROWS : 0;
#pragma unroll
    for (int mi = 0; mi < 2; mi++)
#pragma unroll
        for (int h = 0; h < 2; h++) {
            float v = rs[mi][h];
            v += __shfl_xor_sync(0xffffffffu, v, 1);
            v += __shfl_xor_sync(0xffffffffu, v, 2);
            if (tig == 0) {
                int b = mw + mi * 16 + gid + h * 8;
                atomicAdd(&g_logit[sel + blockIdx.y * B_SZ + b], v);
            }
        }
}

// ---------------- softmax over S (per b), combine weights ----------------
__global__ void softmax_kernel() {
    int b = blockIdx.x;
    int s = threadIdx.x;   // 256 threads == S_LEN
    __shared__ float sv1[S_LEN], sv2[S_LEN];
    float v1 = g_logit[s * B_SZ + b];
    float v2 = g_logit[M_ROWS + s * B_SZ + b];
    sv1[s] = v1; sv2[s] = v2;
    __syncthreads();
    float m1 = -1e30f, m2 = -1e30f;
    for (int i = 0; i < S_LEN; i++) { m1 = fmaxf(m1, sv1[i]); m2 = fmaxf(m2, sv2[i]); }
    float z1 = 0.f, z2 = 0.f;
    for (int i = 0; i < S_LEN; i++) { z1 += expf(sv1[i] - m1); z2 += expf(sv2[i] - m2); }
    float w = (expf(v1 - m1) / z1 + expf(v2 - m2) / z2) * 0.5f / (float)S_LEN;
    g_coef[s * B_SZ + b] = w;
}

// ---------------- weighted sum over S (reads fp16 g_Ah, vectorized) ----------------
__global__ void wsum_kernel(float* __restrict__ out) {
    int b = blockIdx.y;
    int d2 = blockIdx.x * 256 + threadIdx.x;   // half2 index: 512 per b
    __shared__ float as[S_LEN];
    for (int i = threadIdx.x; i < S_LEN; i += 256) as[i] = g_coef[i * B_SZ + b];
    __syncthreads();
    const __half2* p = (const __half2*)g_Ah + (size_t)b * (D1 / 2) + d2;
    float ax = 0.f, ay = 0.f;
#pragma unroll 4
    for (int s = 0; s < S_LEN; s++) {
        float2 v = __half22float2(p[(size_t)s * B_SZ * (D1 / 2)]);
        float w = as[s];
        ax += w * v.x; ay += w * v.y;
    }
    float2 r; r.x = ax; r.y = ay;
    *(float2*)(out + (size_t)b * D1 + d2 * 2) = r;
}

// ---------------- launch ----------------
extern "C" void kernel_launch(void* const* d_in, const int* in_sizes, int n_in,
                              void* d_out, int out_size) {
    const float* f1   = (const float*)d_in[0];
    const float* f2   = (const float*)d_in[1];
    const float* fseq = (const float*)d_in[2];
    const float* W11  = (const float*)d_in[3];
    const float* b11  = (const float*)d_in[4];
    const float* W12  = (const float*)d_in[5];
    const float* b12  = (const float*)d_in[6];
    const float* W21  = (const float*)d_in[7];
    const float* W22  = (const float*)d_in[9];
    float* out = (float*)d_out;

    cudaFuncSetAttribute(small_gemm_kernel, cudaFuncAttributeMaxDynamicSharedMemorySize, SMEM_BYTES_MAIN);
    cudaFuncSetAttribute(main_gemm_kernel,  cudaFuncAttributeMaxDynamicSharedMemorySize, SMEM_BYTES_MAIN);

    prep_kernel<<<512, 256>>>(f1, f2, b11, b12, W21, W22);
    convW_kernel<<<dim3(32, 64), dim3(32, 8)>>>(W11, W12);
    convA_kernel<<<4096, 256>>>(fseq);

    // S-independent terms: g_c (bias-init) += [f1@W11b | f2@W12b], split-K 8
    small_gemm_kernel<<<dim3(16, 1, 8), 256, SMEM_BYTES_MAIN>>>();

    // main fused GEMM (mma.sync, 128x128 tile) + tanh-dot register epilogue -> logits
    main_gemm_kernel<<<dim3(16, 256), 256, SMEM_BYTES_MAIN>>>();

    softmax_kernel<<<128, 256>>>();
    wsum_kernel<<<dim3(2, 128), 256>>>(out);
}